// round 1
// baseline (speedup 1.0000x reference)
#include <cuda_runtime.h>
#include <math.h>

#define BB 64
#define TT 128
#define MMM 4
#define DDIM 512
#define HH 512
#define LLAY 2
#define KKC 6
#define FF 2560   // 5*H

// ---------------- scratch (device globals; no runtime allocation) ----------------
// g_hid[0]: group-sep output (layer0 input seq)
// g_hid[1]: layer0 hidden output / layer1 input seq
// g_hid[2]: layer1 hidden output
__device__ float g_hid[3][BB * TT * 2 * HH];
// g_share[0]: initial share_feat; [1]: layer0 share out; [2]: layer1 share out
__device__ float g_share[3][BB * TT * HH];
// per-step GEMM partials, one slice per K-chunk (deterministic summation)
__device__ float g_part[8][BB * 2 * FF];
// gating weights for current step: [b][j][k]
__device__ float g_w[BB * 2 * KKC];
__device__ float g_cell[BB * 2 * HH];
__device__ float g_sstate[BB * HH];
__device__ float g_cum[BB * HH];

// ---------------- share_feat = relu(feat_flat @ l2s_W + b) ----------------
// A [8192,2048], W [2048,512], C = g_share[0] [8192,512]
// tile 64x128, BK=16, 128 threads, 8x8 micro
__global__ void k_share(const float* __restrict__ A, const float* __restrict__ W,
                        const float* __restrict__ bias) {
    __shared__ float As[16][64];
    __shared__ float Ws[16][128];
    const int n0 = blockIdx.x * 128;
    const int m0 = blockIdx.y * 64;
    const int tid = threadIdx.x;
    const int ty = tid >> 4;       // 0..7
    const int tx = tid & 15;       // 0..15
    const int lm = tid & 63;       // A-load row
    const int lk = (tid >> 6) * 8; // A-load k offset (0 or 8)

    float acc[8][8];
#pragma unroll
    for (int i = 0; i < 8; i++)
#pragma unroll
        for (int jj = 0; jj < 8; jj++) acc[i][jj] = 0.f;

    for (int k0 = 0; k0 < 2048; k0 += 16) {
        const float* ap = A + (long)(m0 + lm) * 2048 + k0 + lk;
        float4 a0 = *(const float4*)ap;
        float4 a1 = *(const float4*)(ap + 4);
        As[lk + 0][lm] = a0.x; As[lk + 1][lm] = a0.y;
        As[lk + 2][lm] = a0.z; As[lk + 3][lm] = a0.w;
        As[lk + 4][lm] = a1.x; As[lk + 5][lm] = a1.y;
        As[lk + 6][lm] = a1.z; As[lk + 7][lm] = a1.w;
#pragma unroll
        for (int q = 0; q < 4; q++) {
            int fi = tid + q * 128;          // 0..511 float4 index
            int wk = fi >> 5;                // 0..15
            int wn = (fi & 31) * 4;          // 0..124
            float4 v = *(const float4*)(W + (long)(k0 + wk) * 512 + n0 + wn);
            *(float4*)&Ws[wk][wn] = v;
        }
        __syncthreads();
#pragma unroll
        for (int k = 0; k < 16; k++) {
            float a[8], w[8];
#pragma unroll
            for (int i = 0; i < 8; i++) a[i] = As[k][ty + i * 8];
#pragma unroll
            for (int jj = 0; jj < 8; jj++) w[jj] = Ws[k][tx + jj * 16];
#pragma unroll
            for (int i = 0; i < 8; i++)
#pragma unroll
                for (int jj = 0; jj < 8; jj++)
                    acc[i][jj] = fmaf(a[i], w[jj], acc[i][jj]);
        }
        __syncthreads();
    }
#pragma unroll
    for (int i = 0; i < 8; i++) {
        int r = m0 + ty + i * 8;
#pragma unroll
        for (int jj = 0; jj < 8; jj++) {
            int cn = n0 + tx + jj * 16;
            float v = acc[i][jj] + bias[cn];
            g_share[0][(long)r * 512 + cn] = fmaxf(v, 0.f);
        }
    }
}

// ---------------- group separation -> g_hid[0] [B,T,2,D] ----------------
__global__ void k_groupsep(const float* __restrict__ feat, const float* __restrict__ sepW,
                           const float* __restrict__ sepb) {
    const int bt = blockIdx.x;       // 0..8191
    const int tid = threadIdx.x;     // 128
    const int warp = tid >> 5, lane = tid & 31;
    __shared__ float sm[4];
    const float* fr = feat + (long)bt * MMM * DDIM;
    if (warp < 4) {
        float s = 0.f;
        const float* f = fr + warp * DDIM;
        for (int d = lane; d < DDIM; d += 32) s += f[d] * sepW[d];
        for (int o = 16; o; o >>= 1) s += __shfl_down_sync(0xffffffffu, s, o);
        if (lane == 0) sm[warp] = s + sepb[0];
    }
    __syncthreads();
    float sc0 = sm[0], sc1 = sm[1], sc2 = sm[2], sc3 = sm[3];
    float mx = fmaxf(fmaxf(sc0, sc1), fmaxf(sc2, sc3));
    float e0 = expf(sc0 - mx), e1 = expf(sc1 - mx), e2 = expf(sc2 - mx), e3 = expf(sc3 - mx);
    float inv = 1.f / (e0 + e1 + e2 + e3);
    float w0 = (e0 * inv - 0.25f) > 0.f ? 1.f : 0.f;
    float w1 = (e1 * inv - 0.25f) > 0.f ? 1.f : 0.f;
    float w2 = (e2 * inv - 0.25f) > 0.f ? 1.f : 0.f;
    float w3 = (e3 * inv - 0.25f) > 0.f ? 1.f : 0.f;
    float n0 = w0 + w1 + w2 + w3;
    float d0 = n0 + 1e-8f;
    float d1 = (4.f - n0) + 1e-8f;
    for (int d = tid; d < DDIM; d += 128) {
        float f0 = fr[d], f1 = fr[DDIM + d], f2 = fr[2 * DDIM + d], f3 = fr[3 * DDIM + d];
        float gs0 = (w0 * f0 + w1 * f1 + w2 * f2 + w3 * f3) / d0;
        float gs1 = ((1.f - w0) * f0 + (1.f - w1) * f1 + (1.f - w2) * f2 + (1.f - w3) * f3) / d1;
        g_hid[0][((long)bt * 2 + 0) * DDIM + d] = gs0;
        g_hid[0][((long)bt * 2 + 1) * DDIM + d] = gs1;
    }
}

// ---------------- per-layer state init ----------------
__global__ void k_layerinit() {
    int i = blockIdx.x * blockDim.x + threadIdx.x;
    if (i < BB * 2 * HH) g_cell[i] = 0.f;
    if (i < BB * HH) { g_sstate[i] = 0.f; g_cum[i] = 0.f; }
}

// ---------------- gating: logits = h1 @ aW[l] + ab[l]; hard top-2 ----------------
__global__ void k_gate(int l, int t, const float* __restrict__ aW, const float* __restrict__ ab) {
    const int bj = blockIdx.x;        // 0..127
    const int b = bj >> 1, j = bj & 1;
    const int tid = threadIdx.x;      // 192 (6 warps)
    const int warp = tid >> 5, lane = tid & 31;
    __shared__ float lg[KKC];
    __shared__ int si1, si2;
    if (warp < KKC) {
        float s = 0.f;
        if (t > 0) {
            const float* h1 = &g_hid[l + 1][((long)(b * TT + t - 1) * 2 + j) * HH];
            const float* w = aW + (long)l * HH * KKC + warp;
            for (int d = lane; d < HH; d += 32) s += h1[d] * w[d * KKC];
        }
        for (int o = 16; o; o >>= 1) s += __shfl_down_sync(0xffffffffu, s, o);
        if (lane == 0) lg[warp] = s + ab[l * KKC + warp];
    }
    __syncthreads();
    if (tid == 0) {
        int i1 = 0;
        for (int k = 1; k < KKC; k++) if (lg[k] > lg[i1]) i1 = k;
        int i2 = (i1 == 0) ? 1 : 0;
        for (int k = 0; k < KKC; k++) if (k != i1 && lg[k] > lg[i2]) i2 = k;
        si1 = i1; si2 = i2;
    }
    __syncthreads();
    if (tid < KKC)
        g_w[bj * KKC + tid] = (tid == si1 || tid == si2) ? 0.5f : 0.f;
}

// ---------------- per-step GEMM: one K-chunk (512) into g_part[c] ----------------
// C[b, n] (per j) = A_c[b, 0:512] @ W_c[512, 2560-tile], A rows gathered+scaled.
__global__ void k_stepgemm(int l, int t, const float* __restrict__ ctx,
                           const float* __restrict__ Wx, const float* __restrict__ Wh,
                           const float* __restrict__ Wc) {
    const int n0 = blockIdx.x * 128;
    const int j = blockIdx.y;
    const int c = blockIdx.z;
    const float* seq = g_hid[l];
    const float* hout = g_hid[l + 1];

    const float* Wmat;
    {
        long woff = (long)(l * 2 + j) * DDIM * FF;
        if (c == 0) Wmat = Wx + woff;
        else if (c == 1) Wmat = Wh + woff;
        else Wmat = Wc + ((long)((l * 2 + j) * KKC) + (c - 2)) * DDIM * FF;
    }

    __shared__ const float* sp[64];
    __shared__ float scs[64];
    __shared__ float As[16][64];
    __shared__ float Ws[16][128];

    const int tid = threadIdx.x;   // 128
    if (tid < 64) {
        const int b = tid;
        const float* p = 0; float s = 1.f;
        switch (c) {
            case 0: p = seq + ((long)(b * TT + t) * 2 + j) * DDIM; break;
            case 1: p = (t > 0) ? hout + ((long)(b * TT + t - 1) * 2 + j) * DDIM : 0; break;
            case 2: p = (t > 1) ? hout + ((long)(b * TT + t - 2) * 2 + j) * DDIM : 0;
                    s = g_w[(b * 2 + j) * KKC + 0]; break;
            case 3: p = (t < TT - 1) ? seq + ((long)(b * TT + t + 1) * 2 + j) * DDIM : 0;
                    s = g_w[(b * 2 + j) * KKC + 1]; break;
            case 4: p = (t > 0) ? hout + ((long)(b * TT + t - 1) * 2 + (1 - j)) * DDIM : 0;
                    s = g_w[(b * 2 + j) * KKC + 2]; break;
            case 5: p = seq + ((long)(b * TT + t) * 2 + (1 - j)) * DDIM;
                    s = g_w[(b * 2 + j) * KKC + 3]; break;
            case 6: p = (t < TT - 1) ? seq + ((long)(b * TT + t + 1) * 2 + (1 - j)) * DDIM : 0;
                    s = g_w[(b * 2 + j) * KKC + 4]; break;
            case 7: p = ctx + (long)(b * TT + t) * HH;
                    s = g_w[(b * 2 + j) * KKC + 5]; break;
        }
        if (s == 0.f) p = 0;
        sp[b] = p; scs[b] = s;
    }
    __syncthreads();

    const int ty = tid >> 4;       // 0..7
    const int tx = tid & 15;       // 0..15
    const int lm = tid & 63;
    const int lk = (tid >> 6) * 8;

    float acc[8][8];
#pragma unroll
    for (int i = 0; i < 8; i++)
#pragma unroll
        for (int jj = 0; jj < 8; jj++) acc[i][jj] = 0.f;

    const float* myp = sp[lm];
    const float mys = scs[lm];

    for (int k0 = 0; k0 < 512; k0 += 16) {
        float4 a0 = make_float4(0.f, 0.f, 0.f, 0.f), a1 = a0;
        if (myp) {
            a0 = *(const float4*)(myp + k0 + lk);
            a1 = *(const float4*)(myp + k0 + lk + 4);
        }
        As[lk + 0][lm] = a0.x * mys; As[lk + 1][lm] = a0.y * mys;
        As[lk + 2][lm] = a0.z * mys; As[lk + 3][lm] = a0.w * mys;
        As[lk + 4][lm] = a1.x * mys; As[lk + 5][lm] = a1.y * mys;
        As[lk + 6][lm] = a1.z * mys; As[lk + 7][lm] = a1.w * mys;
#pragma unroll
        for (int q = 0; q < 4; q++) {
            int fi = tid + q * 128;
            int wk = fi >> 5;
            int wn = (fi & 31) * 4;
            float4 v = *(const float4*)(Wmat + (long)(k0 + wk) * FF + n0 + wn);
            *(float4*)&Ws[wk][wn] = v;
        }
        __syncthreads();
#pragma unroll
        for (int k = 0; k < 16; k++) {
            float a[8], w[8];
#pragma unroll
            for (int i = 0; i < 8; i++) a[i] = As[k][ty + i * 8];
#pragma unroll
            for (int jj = 0; jj < 8; jj++) w[jj] = Ws[k][tx + jj * 16];
#pragma unroll
            for (int i = 0; i < 8; i++)
#pragma unroll
                for (int jj = 0; jj < 8; jj++)
                    acc[i][jj] = fmaf(a[i], w[jj], acc[i][jj]);
        }
        __syncthreads();
    }
    // plain store into this chunk's partial slice (deterministic)
#pragma unroll
    for (int i = 0; i < 8; i++) {
        int b = ty + i * 8;
        long base = ((long)b * 2 + j) * FF + n0;
#pragma unroll
        for (int jj = 0; jj < 8; jj++)
            g_part[c][base + tx + jj * 16] = acc[i][jj];
    }
}

// ---------------- pointwise: sum partials, biases, LSTM update, share update ----------------
__global__ void k_point(int l, int t,
                        const float* __restrict__ bx, const float* __restrict__ bh,
                        const float* __restrict__ cb) {
    const int b = blockIdx.x;     // 64
    const int u = threadIdx.x;    // 512
    const float* sharein = g_share[l];
    float* shareout = g_share[l + 1];
    float* hout = g_hid[l + 1];

    float sgsum = 0.f;
#pragma unroll
    for (int j = 0; j < 2; j++) {
        long base = ((long)b * 2 + j) * FF;
        float wv[KKC];
#pragma unroll
        for (int k = 0; k < KKC; k++) wv[k] = g_w[(b * 2 + j) * KKC + k];
        float g[5];
#pragma unroll
        for (int gi = 0; gi < 5; gi++) {
            long fidx = (long)gi * HH + u;
            float v = 0.f;
#pragma unroll
            for (int c = 0; c < 8; c++) v += g_part[c][base + fidx];
            long bidx = (long)(l * 2 + j) * FF + fidx;
            v += bx[bidx] + bh[bidx];
#pragma unroll
            for (int k = 0; k < KKC; k++)
                v += wv[k] * cb[((long)(l * 2 + j) * KKC + k) * FF + fidx];
            g[gi] = v;
        }
        long ci = (long)(b * 2 + j) * HH + u;
        float cell = g_cell[ci];
        float si = 1.f / (1.f + expf(-g[0]));
        float sf = 1.f / (1.f + expf(-g[1]));
        float so = 1.f / (1.f + expf(-g[2]));
        float cn = (1.f - sf) * cell + si * tanhf(g[4]);
        g_cell[ci] = cn;
        float h = so * tanhf(cn);
        hout[((long)(b * TT + t) * 2 + j) * HH + u] = h;
        sgsum += g[3];
    }
    float gate = 1.f / (1.f + expf(-sgsum));
    long su = (long)b * HH + u;
    float ss = g_sstate[su] + gate * sharein[((long)b * TT + t) * HH + u];
    float cm = g_cum[su] + gate;
    g_sstate[su] = ss; g_cum[su] = cm;
    shareout[((long)b * TT + t) * HH + u] = ss / cm;
}

// ---------------- final combine ----------------
__global__ void k_final(float* __restrict__ out) {
    long i = (long)blockIdx.x * blockDim.x + threadIdx.x;
    const long total = (long)BB * TT * 1536;
    if (i >= total) return;
    long bt = i / 1536;
    int f = (int)(i % 1536);
    float v;
    if (f < 1024)
        v = 0.5f * (g_hid[1][bt * 1024 + f] + g_hid[2][bt * 1024 + f]);
    else {
        int u = f - 1024;
        v = 0.5f * (g_share[1][bt * HH + u] + g_share[2][bt * HH + u]);
    }
    out[i] = v;
}

// ---------------- launch ----------------
extern "C" void kernel_launch(void* const* d_in, const int* in_sizes, int n_in,
                              void* d_out, int out_size) {
    (void)in_sizes; (void)n_in; (void)out_size;
    const float* feat = (const float*)d_in[0];
    const float* ctx  = (const float*)d_in[1];
    const float* l2sW = (const float*)d_in[2];
    const float* l2sb = (const float*)d_in[3];
    const float* sepW = (const float*)d_in[4];
    const float* sepb = (const float*)d_in[5];
    const float* aW   = (const float*)d_in[6];
    const float* ab   = (const float*)d_in[7];
    const float* Wx   = (const float*)d_in[8];
    const float* bx   = (const float*)d_in[9];
    const float* Wh   = (const float*)d_in[10];
    const float* bh   = (const float*)d_in[11];
    const float* Wc   = (const float*)d_in[12];
    const float* cb   = (const float*)d_in[13];
    float* out = (float*)d_out;

    k_share<<<dim3(4, 128), 128>>>(feat, l2sW, l2sb);
    k_groupsep<<<BB * TT, 128>>>(feat, sepW, sepb);
    for (int l = 0; l < LLAY; l++) {
        k_layerinit<<<(BB * 2 * HH + 255) / 256, 256>>>();
        for (int t = 0; t < TT; t++) {
            k_gate<<<BB * 2, 192>>>(l, t, aW, ab);
            k_stepgemm<<<dim3(20, 2, 8), 128>>>(l, t, ctx, Wx, Wh, Wc);
            k_point<<<BB, 512>>>(l, t, bx, bh, cb);
        }
    }
    k_final<<<((BB * TT * 1536) + 255) / 256, 256>>>(out);
}